// round 3
// baseline (speedup 1.0000x reference)
#include <cuda_runtime.h>
#include <cuda_fp16.h>
#include <cstdint>

// ============================ config ============================
#define K_DIM 1024
#define N_DIM 1024
#define BM 128
#define BN 256
#define BK 64
#define KTILES (K_DIM / BK)   // 16
#define NSTAGE 4
#define THREADS 256

#define A_STAGE (BM * BK * 2)                 // 16384 B
#define B_STAGE (BN * BK * 2)                 // 32768 B
#define SMEM_BIAS  0
#define SMEM_MW    1024
#define SMEM_TILES 2048
#define SMEM_TOTAL (SMEM_TILES + NSTAGE * (A_STAGE + B_STAGE))  // 198656 B

// static scratch (allocation-free rule: __device__ globals)
__device__ __half g_xh[(size_t)65536 * K_DIM];   // x converted to fp16
__device__ __half g_Wt[(size_t)N_DIM * K_DIM];   // W transposed to (N,K) fp16

// ============================ helpers ============================
__device__ __forceinline__ uint32_t smem_u32(const void* p) {
    uint32_t a;
    asm("{ .reg .u64 t; cvta.to.shared.u64 t, %1; cvt.u32.u64 %0, t; }"
        : "=r"(a) : "l"(p));
    return a;
}

__device__ __forceinline__ void cp_async16(uint32_t dst, const void* src) {
    asm volatile("cp.async.cg.shared.global [%0], [%1], 16;" :: "r"(dst), "l"(src));
}
#define CP_COMMIT() asm volatile("cp.async.commit_group;" ::: "memory")
#define CP_WAIT(n)  asm volatile("cp.async.wait_group %0;" :: "n"(n) : "memory")

__device__ __forceinline__ void ldsm_x4(uint32_t& r0, uint32_t& r1,
                                        uint32_t& r2, uint32_t& r3, uint32_t addr) {
    asm volatile("ldmatrix.sync.aligned.m8n8.x4.shared.b16 {%0,%1,%2,%3}, [%4];"
                 : "=r"(r0), "=r"(r1), "=r"(r2), "=r"(r3) : "r"(addr));
}

__device__ __forceinline__ void mma16816(float* d, const uint32_t* a,
                                         uint32_t b0, uint32_t b1) {
    asm volatile(
        "mma.sync.aligned.m16n8k16.row.col.f32.f16.f16.f32 "
        "{%0,%1,%2,%3}, {%4,%5,%6,%7}, {%8,%9}, {%0,%1,%2,%3};"
        : "+f"(d[0]), "+f"(d[1]), "+f"(d[2]), "+f"(d[3])
        : "r"(a[0]), "r"(a[1]), "r"(a[2]), "r"(a[3]), "r"(b0), "r"(b1));
}

// sigmoid via single-MUFU tanh.approx: sig(v) = 0.5*tanh(0.5v) + 0.5
__device__ __forceinline__ float fsig(float v) {
    float t;
    asm("tanh.approx.f32 %0, %1;" : "=f"(t) : "f"(v * 0.5f));
    return fmaf(0.5f, t, 0.5f);
}

// ============================ pre-pass kernels ============================
// x fp32 -> fp16 (8 elements / thread)
__global__ void convert_x_kernel(const float* __restrict__ x) {
    size_t i = ((size_t)blockIdx.x * THREADS + threadIdx.x) * 8;
    float4 f0 = *reinterpret_cast<const float4*>(x + i);
    float4 f1 = *reinterpret_cast<const float4*>(x + i + 4);
    __half2 h0 = __floats2half2_rn(f0.x, f0.y);
    __half2 h1 = __floats2half2_rn(f0.z, f0.w);
    __half2 h2 = __floats2half2_rn(f1.x, f1.y);
    __half2 h3 = __floats2half2_rn(f1.z, f1.w);
    uint4 o;
    o.x = *reinterpret_cast<uint32_t*>(&h0);
    o.y = *reinterpret_cast<uint32_t*>(&h1);
    o.z = *reinterpret_cast<uint32_t*>(&h2);
    o.w = *reinterpret_cast<uint32_t*>(&h3);
    *reinterpret_cast<uint4*>(&g_xh[i]) = o;
}

// W (K,N) fp32 -> Wt (N,K) fp16
__global__ void transpose_W_kernel(const float* __restrict__ W) {
    __shared__ float t[32][33];
    int n = blockIdx.x * 32 + threadIdx.x;
    int k = blockIdx.y * 32 + threadIdx.y;
#pragma unroll
    for (int i = 0; i < 4; ++i)
        t[threadIdx.y + i * 8][threadIdx.x] = W[(size_t)(k + i * 8) * N_DIM + n];
    __syncthreads();
    int n2 = blockIdx.x * 32 + threadIdx.y;
    int k2 = blockIdx.y * 32 + threadIdx.x;
#pragma unroll
    for (int i = 0; i < 4; ++i)
        g_Wt[(size_t)(n2 + i * 8) * K_DIM + k2] = __float2half(t[threadIdx.x][threadIdx.y + i * 8]);
}

// ============================ pipeline loads ============================
// One stage: A 128x64 fp16 (16KB) + B 256x64 fp16 (32KB), 16B cp.async chunks,
// xor-swizzled 128B rows (chunk c of row r stored at (c ^ (r&7))).
__device__ __forceinline__ void load_stage(uint32_t dstA, uint32_t dstB,
                                           const __half* __restrict__ ag,
                                           const __half* __restrict__ bg, int tid) {
#pragma unroll
    for (int i = 0; i < 4; ++i) {
        int id = i * THREADS + tid;
        int r = id >> 3, c = id & 7;
        cp_async16(dstA + r * 128 + (((c ^ (r & 7))) << 4), ag + (size_t)r * K_DIM + c * 8);
    }
#pragma unroll
    for (int i = 0; i < 8; ++i) {
        int id = i * THREADS + tid;
        int r = id >> 3, c = id & 7;
        cp_async16(dstB + r * 128 + (((c ^ (r & 7))) << 4), bg + (size_t)r * K_DIM + c * 8);
    }
}

// ============================ main fused kernel ============================
__global__ __launch_bounds__(THREADS, 1)
void fused_gemm_gn_swish_kernel(const float* __restrict__ bias,
                                const float* __restrict__ mw,
                                float* __restrict__ out) {
    extern __shared__ char smem[];
    uint32_t sb = smem_u32(smem);
    const int tid  = threadIdx.x;
    const int lane = tid & 31;
    const int wid  = tid >> 5;
    const int wm   = wid >> 2;   // 0..1  (M warp row, 64 rows each)
    const int wn   = wid & 3;    // 0..3  (N warp col, 64 cols = two GN groups)
    const int m0   = blockIdx.y * BM;
    const int n0   = blockIdx.x * BN;

    float* sbias = (float*)(smem + SMEM_BIAS);
    float* smw   = (float*)(smem + SMEM_MW);
    if (tid < BN) {
        sbias[tid] = bias[n0 + tid];
        smw[tid]   = mw[n0 + tid];
    }

    const __half* ag = g_xh + (size_t)m0 * K_DIM;
    const __half* bg = g_Wt + (size_t)n0 * K_DIM;
    uint32_t sA = sb + SMEM_TILES;
    uint32_t sB = sA + NSTAGE * A_STAGE;

    // prefetch NSTAGE-1 stages
#pragma unroll
    for (int s = 0; s < NSTAGE - 1; ++s) {
        load_stage(sA + s * A_STAGE, sB + s * B_STAGE, ag + s * BK, bg + s * BK, tid);
        CP_COMMIT();
    }

    float acc[4][8][4];
#pragma unroll
    for (int i = 0; i < 4; ++i)
#pragma unroll
        for (int j = 0; j < 8; ++j)
#pragma unroll
            for (int e = 0; e < 4; ++e) acc[i][j][e] = 0.0f;

    // ldmatrix lane addressing (swizzle offset is row-group independent:
    // r&7 == lrow&7 because all row offsets are multiples of 16)
    const int lrow   = lane & 15;
    const int lchunk = lane >> 4;
    const uint32_t aRow = (uint32_t)(wm * 64 + lrow) * 128;
    const uint32_t bRow = (uint32_t)(wn * 64 + lrow) * 128;
    uint32_t soff[4];
#pragma unroll
    for (int ks = 0; ks < 4; ++ks)
        soff[ks] = (uint32_t)(((ks * 2 + lchunk) ^ (lrow & 7)) << 4);

    int buf = 0, ibuf = NSTAGE - 1;
    for (int kt = 0; kt < KTILES; ++kt) {
        if (kt < KTILES - 2)       { CP_WAIT(2); }
        else if (kt == KTILES - 2) { CP_WAIT(1); }
        else                       { CP_WAIT(0); }
        __syncthreads();

        // issue stage kt+NSTAGE-1 (overwrites buffer of stage kt-1, protected by sync)
        if (kt + NSTAGE - 1 < KTILES) {
            load_stage(sA + ibuf * A_STAGE, sB + ibuf * B_STAGE,
                       ag + (kt + NSTAGE - 1) * BK, bg + (kt + NSTAGE - 1) * BK, tid);
            CP_COMMIT();
            if (++ibuf == NSTAGE) ibuf = 0;
        }

        uint32_t aB = sA + buf * A_STAGE + aRow;
        uint32_t bB = sB + buf * B_STAGE + bRow;
#pragma unroll
        for (int ks = 0; ks < 4; ++ks) {
            uint32_t a[4][4], b[4][4];
#pragma unroll
            for (int mi = 0; mi < 4; ++mi)
                ldsm_x4(a[mi][0], a[mi][1], a[mi][2], a[mi][3],
                        aB + mi * (16 * 128) + soff[ks]);
#pragma unroll
            for (int p = 0; p < 4; ++p)
                ldsm_x4(b[p][0], b[p][1], b[p][2], b[p][3],
                        bB + p * (16 * 128) + soff[ks]);
            // b[p][0]=n(lo,p) k0-7, b[p][1]=n(hi,p) k0-7, b[p][2]=k8-15 lo, b[p][3]=k8-15 hi
#pragma unroll
            for (int mi = 0; mi < 4; ++mi) {
#pragma unroll
                for (int ni = 0; ni < 8; ++ni) {
                    uint32_t b0 = (ni & 1) ? b[ni >> 1][1] : b[ni >> 1][0];
                    uint32_t b1 = (ni & 1) ? b[ni >> 1][3] : b[ni >> 1][2];
                    mma16816(acc[mi][ni], a[mi], b0, b1);
                }
            }
        }
        if (++buf == NSTAGE) buf = 0;
    }

    // -------- fused epilogue: bias + GroupNorm(32ch) + swish * w * swish --------
    // Each 32-channel group = 4 consecutive ni blocks; mean/var reduce across the
    // lane quad only (shfl.xor 1,2).
    const int q  = lane >> 2;   // fragment row within 8-row group
    const int qt = lane & 3;    // fragment col pair selector
    const float inv32 = 1.0f / 32.0f;

#pragma unroll
    for (int mi = 0; mi < 4; ++mi) {
#pragma unroll
        for (int half = 0; half < 2; ++half) {
            int row = m0 + wm * 64 + mi * 16 + half * 8 + q;
            float* op = out + (size_t)row * N_DIM + n0 + wn * 64;
#pragma unroll
            for (int g2 = 0; g2 < 2; ++g2) {     // two 32-ch groups per warp tile
                float v[8];
                float sum = 0.0f, ssq = 0.0f;
#pragma unroll
                for (int nj = 0; nj < 4; ++nj) {
                    int ni = g2 * 4 + nj;
#pragma unroll
                    for (int e = 0; e < 2; ++e) {
                        float val = acc[mi][ni][half * 2 + e]
                                  + sbias[wn * 64 + ni * 8 + qt * 2 + e];
                        v[nj * 2 + e] = val;
                        sum += val;
                        ssq = fmaf(val, val, ssq);
                    }
                }
                sum += __shfl_xor_sync(0xffffffffu, sum, 1);
                ssq += __shfl_xor_sync(0xffffffffu, ssq, 1);
                sum += __shfl_xor_sync(0xffffffffu, sum, 2);
                ssq += __shfl_xor_sync(0xffffffffu, ssq, 2);
                float mean = sum * inv32;
                float var  = fmaf(ssq, inv32, -mean * mean);
                float rstd = rsqrtf(var + 1e-5f);

#pragma unroll
                for (int nj = 0; nj < 4; ++nj) {
                    int ni = g2 * 4 + nj;
                    float2 o;
#pragma unroll
                    for (int e = 0; e < 2; ++e) {
                        float nv = (v[nj * 2 + e] - mean) * rstd;
                        float s  = nv * fsig(nv);
                        float mm = s * smw[wn * 64 + ni * 8 + qt * 2 + e];
                        float ov = mm * fsig(mm);
                        if (e == 0) o.x = ov; else o.y = ov;
                    }
                    *reinterpret_cast<float2*>(op + ni * 8 + qt * 2) = o;
                }
            }
        }
    }
}

// ============================ launch ============================
extern "C" void kernel_launch(void* const* d_in, const int* in_sizes, int n_in,
                              void* d_out, int out_size) {
    const float* x  = (const float*)d_in[0];
    const float* W  = (const float*)d_in[1];
    const float* b  = (const float*)d_in[2];
    const float* mw = (const float*)d_in[3];
    float* out = (float*)d_out;

    const size_t M = (size_t)in_sizes[0] / K_DIM;   // 65536

    // 1) x -> fp16
    convert_x_kernel<<<(unsigned)(M * K_DIM / 8 / THREADS), THREADS>>>(x);

    // 2) W -> Wt fp16
    dim3 tb(32, 8), tg(N_DIM / 32, K_DIM / 32);
    transpose_W_kernel<<<tg, tb>>>(W);

    // 3) fused GEMM + bias + GroupNorm + Swish chain
    cudaFuncSetAttribute(fused_gemm_gn_swish_kernel,
                         cudaFuncAttributeMaxDynamicSharedMemorySize, SMEM_TOTAL);
    dim3 grid(N_DIM / BN, (unsigned)(M / BM));  // x fastest: N-tiles of one M share A in L2
    fused_gemm_gn_swish_kernel<<<grid, THREADS, SMEM_TOTAL>>>(b, mw, out);
}

// round 4
// speedup vs baseline: 1.0717x; 1.0717x over previous
#include <cuda_runtime.h>
#include <cuda_fp16.h>
#include <cstdint>

// ============================ config ============================
#define K_DIM 1024
#define N_DIM 1024
#define BM 128
#define BN 128
#define BK 64
#define KTILES (K_DIM / BK)   // 16
#define NSTAGE 3
#define THREADS 128

#define A_STAGE (BM * BK * 2)                 // 16384 B
#define B_STAGE (BN * BK * 2)                 // 16384 B
#define SMEM_BIAS  0
#define SMEM_MW    512
#define SMEM_TILES 1024
#define SMEM_TOTAL (SMEM_TILES + NSTAGE * (A_STAGE + B_STAGE))  // 99328 B

// static scratch (allocation-free rule: __device__ globals)
__device__ __half g_xh[(size_t)65536 * K_DIM];   // x converted to fp16
__device__ __half g_Wt[(size_t)N_DIM * K_DIM];   // W transposed to (N,K) fp16

// ============================ helpers ============================
__device__ __forceinline__ uint32_t smem_u32(const void* p) {
    uint32_t a;
    asm("{ .reg .u64 t; cvta.to.shared.u64 t, %1; cvt.u32.u64 %0, t; }"
        : "=r"(a) : "l"(p));
    return a;
}

__device__ __forceinline__ void cp_async16(uint32_t dst, const void* src) {
    asm volatile("cp.async.cg.shared.global [%0], [%1], 16;" :: "r"(dst), "l"(src));
}
#define CP_COMMIT() asm volatile("cp.async.commit_group;" ::: "memory")
#define CP_WAIT(n)  asm volatile("cp.async.wait_group %0;" :: "n"(n) : "memory")

__device__ __forceinline__ void ldsm_x4(uint32_t& r0, uint32_t& r1,
                                        uint32_t& r2, uint32_t& r3, uint32_t addr) {
    asm volatile("ldmatrix.sync.aligned.m8n8.x4.shared.b16 {%0,%1,%2,%3}, [%4];"
                 : "=r"(r0), "=r"(r1), "=r"(r2), "=r"(r3) : "r"(addr));
}

__device__ __forceinline__ void mma16816(float* d, const uint32_t* a,
                                         uint32_t b0, uint32_t b1) {
    asm volatile(
        "mma.sync.aligned.m16n8k16.row.col.f32.f16.f16.f32 "
        "{%0,%1,%2,%3}, {%4,%5,%6,%7}, {%8,%9}, {%0,%1,%2,%3};"
        : "+f"(d[0]), "+f"(d[1]), "+f"(d[2]), "+f"(d[3])
        : "r"(a[0]), "r"(a[1]), "r"(a[2]), "r"(a[3]), "r"(b0), "r"(b1));
}

// sigmoid via single-MUFU tanh.approx: sig(v) = 0.5*tanh(0.5v) + 0.5
__device__ __forceinline__ float fsig(float v) {
    float t;
    asm("tanh.approx.f32 %0, %1;" : "=f"(t) : "f"(v * 0.5f));
    return fmaf(0.5f, t, 0.5f);
}

// ============================ pre-pass kernels ============================
// x fp32 -> fp16 (8 elements / thread)
__global__ void convert_x_kernel(const float* __restrict__ x) {
    size_t i = ((size_t)blockIdx.x * 256 + threadIdx.x) * 8;
    float4 f0 = *reinterpret_cast<const float4*>(x + i);
    float4 f1 = *reinterpret_cast<const float4*>(x + i + 4);
    __half2 h0 = __floats2half2_rn(f0.x, f0.y);
    __half2 h1 = __floats2half2_rn(f0.z, f0.w);
    __half2 h2 = __floats2half2_rn(f1.x, f1.y);
    __half2 h3 = __floats2half2_rn(f1.z, f1.w);
    uint4 o;
    o.x = *reinterpret_cast<uint32_t*>(&h0);
    o.y = *reinterpret_cast<uint32_t*>(&h1);
    o.z = *reinterpret_cast<uint32_t*>(&h2);
    o.w = *reinterpret_cast<uint32_t*>(&h3);
    *reinterpret_cast<uint4*>(&g_xh[i]) = o;
}

// W (K,N) fp32 -> Wt (N,K) fp16
__global__ void transpose_W_kernel(const float* __restrict__ W) {
    __shared__ float t[32][33];
    int n = blockIdx.x * 32 + threadIdx.x;
    int k = blockIdx.y * 32 + threadIdx.y;
#pragma unroll
    for (int i = 0; i < 4; ++i)
        t[threadIdx.y + i * 8][threadIdx.x] = W[(size_t)(k + i * 8) * N_DIM + n];
    __syncthreads();
    int n2 = blockIdx.x * 32 + threadIdx.y;
    int k2 = blockIdx.y * 32 + threadIdx.x;
#pragma unroll
    for (int i = 0; i < 4; ++i)
        g_Wt[(size_t)(n2 + i * 8) * K_DIM + k2] = __float2half(t[threadIdx.x][threadIdx.y + i * 8]);
}

// ============================ pipeline loads ============================
// One stage: A 128x64 fp16 (16KB) + B 128x64 fp16 (16KB), 16B cp.async chunks,
// xor-swizzled 128B rows (chunk c of row r stored at (c ^ (r&7))).
__device__ __forceinline__ void load_stage(uint32_t dstA, uint32_t dstB,
                                           const __half* __restrict__ ag,
                                           const __half* __restrict__ bg, int tid) {
#pragma unroll
    for (int i = 0; i < 8; ++i) {
        int id = i * THREADS + tid;
        int r = id >> 3, c = id & 7;
        cp_async16(dstA + r * 128 + (((c ^ (r & 7))) << 4), ag + (size_t)r * K_DIM + c * 8);
    }
#pragma unroll
    for (int i = 0; i < 8; ++i) {
        int id = i * THREADS + tid;
        int r = id >> 3, c = id & 7;
        cp_async16(dstB + r * 128 + (((c ^ (r & 7))) << 4), bg + (size_t)r * K_DIM + c * 8);
    }
}

// ============================ main fused kernel ============================
// 4 warps in 2x2; each warp computes a 64x64 tile (acc[4][8][4], 128 regs).
__global__ __launch_bounds__(THREADS, 2)
void fused_gemm_gn_swish_kernel(const float* __restrict__ bias,
                                const float* __restrict__ mw,
                                float* __restrict__ out) {
    extern __shared__ char smem[];
    uint32_t sb = smem_u32(smem);
    const int tid  = threadIdx.x;
    const int lane = tid & 31;
    const int wid  = tid >> 5;
    const int wm   = wid >> 1;   // 0..1  (M warp row, 64 rows each)
    const int wn   = wid & 1;    // 0..1  (N warp col, 64 cols = two GN groups)
    const int m0   = blockIdx.y * BM;
    const int n0   = blockIdx.x * BN;

    float* sbias = (float*)(smem + SMEM_BIAS);
    float* smw   = (float*)(smem + SMEM_MW);
    if (tid < BN) {
        sbias[tid] = bias[n0 + tid];
        smw[tid]   = mw[n0 + tid];
    }

    const __half* ag = g_xh + (size_t)m0 * K_DIM;
    const __half* bg = g_Wt + (size_t)n0 * K_DIM;
    uint32_t sA = sb + SMEM_TILES;
    uint32_t sB = sA + NSTAGE * A_STAGE;

    // prefetch 2 stages
    load_stage(sA, sB, ag, bg, tid);
    CP_COMMIT();
    load_stage(sA + A_STAGE, sB + B_STAGE, ag + BK, bg + BK, tid);
    CP_COMMIT();

    float acc[4][8][4];
#pragma unroll
    for (int i = 0; i < 4; ++i)
#pragma unroll
        for (int j = 0; j < 8; ++j)
#pragma unroll
            for (int e = 0; e < 4; ++e) acc[i][j][e] = 0.0f;

    // ldmatrix lane addressing (swizzle offset is row-group independent:
    // r&7 == lrow&7 because all row offsets are multiples of 16)
    const int lrow   = lane & 15;
    const int lchunk = lane >> 4;
    const uint32_t aRow = (uint32_t)(wm * 64 + lrow) * 128;
    const uint32_t bRow = (uint32_t)(wn * 64 + lrow) * 128;
    uint32_t soff[4];
#pragma unroll
    for (int ks = 0; ks < 4; ++ks)
        soff[ks] = (uint32_t)(((ks * 2 + lchunk) ^ (lrow & 7)) << 4);

    int buf = 0, ibuf = 2;
    for (int kt = 0; kt < KTILES; ++kt) {
        if (kt < KTILES - 1) { CP_WAIT(1); } else { CP_WAIT(0); }
        __syncthreads();

        // issue stage kt+2 (overwrites buffer of stage kt-1, protected by the sync)
        if (kt + 2 < KTILES) {
            load_stage(sA + ibuf * A_STAGE, sB + ibuf * B_STAGE,
                       ag + (kt + 2) * BK, bg + (kt + 2) * BK, tid);
            CP_COMMIT();
            if (++ibuf == NSTAGE) ibuf = 0;
        }

        uint32_t aB = sA + buf * A_STAGE + aRow;
        uint32_t bB = sB + buf * B_STAGE + bRow;
#pragma unroll
        for (int ks = 0; ks < 4; ++ks) {
            uint32_t a[4][4], b[4][4];
#pragma unroll
            for (int mi = 0; mi < 4; ++mi)
                ldsm_x4(a[mi][0], a[mi][1], a[mi][2], a[mi][3],
                        aB + mi * (16 * 128) + soff[ks]);
#pragma unroll
            for (int p = 0; p < 4; ++p)
                ldsm_x4(b[p][0], b[p][1], b[p][2], b[p][3],
                        bB + p * (16 * 128) + soff[ks]);
            // b[p][0]=n(lo,p) k0-7, b[p][1]=n(hi,p) k0-7, b[p][2]=k8-15 lo, b[p][3]=k8-15 hi
#pragma unroll
            for (int mi = 0; mi < 4; ++mi) {
#pragma unroll
                for (int ni = 0; ni < 8; ++ni) {
                    uint32_t b0 = (ni & 1) ? b[ni >> 1][1] : b[ni >> 1][0];
                    uint32_t b1 = (ni & 1) ? b[ni >> 1][3] : b[ni >> 1][2];
                    mma16816(acc[mi][ni], a[mi], b0, b1);
                }
            }
        }
        if (++buf == NSTAGE) buf = 0;
    }

    // -------- fused epilogue: bias + GroupNorm(32ch) + swish * w * swish --------
    // Each 32-channel group = 4 consecutive ni blocks; mean/var reduce across the
    // lane quad only (shfl.xor 1,2).
    const int q  = lane >> 2;   // fragment row within 8-row group
    const int qt = lane & 3;    // fragment col pair selector
    const float inv32 = 1.0f / 32.0f;

#pragma unroll
    for (int mi = 0; mi < 4; ++mi) {
#pragma unroll
        for (int half = 0; half < 2; ++half) {
            int row = m0 + wm * 64 + mi * 16 + half * 8 + q;
            float* op = out + (size_t)row * N_DIM + n0 + wn * 64;
#pragma unroll
            for (int g2 = 0; g2 < 2; ++g2) {     // two 32-ch groups per warp tile
                float v[8];
                float sum = 0.0f, ssq = 0.0f;
#pragma unroll
                for (int nj = 0; nj < 4; ++nj) {
                    int ni = g2 * 4 + nj;
#pragma unroll
                    for (int e = 0; e < 2; ++e) {
                        float val = acc[mi][ni][half * 2 + e]
                                  + sbias[wn * 64 + ni * 8 + qt * 2 + e];
                        v[nj * 2 + e] = val;
                        sum += val;
                        ssq = fmaf(val, val, ssq);
                    }
                }
                sum += __shfl_xor_sync(0xffffffffu, sum, 1);
                ssq += __shfl_xor_sync(0xffffffffu, ssq, 1);
                sum += __shfl_xor_sync(0xffffffffu, sum, 2);
                ssq += __shfl_xor_sync(0xffffffffu, ssq, 2);
                float mean = sum * inv32;
                float var  = fmaf(ssq, inv32, -mean * mean);
                float rstd = rsqrtf(var + 1e-5f);

#pragma unroll
                for (int nj = 0; nj < 4; ++nj) {
                    int ni = g2 * 4 + nj;
                    float2 o;
#pragma unroll
                    for (int e = 0; e < 2; ++e) {
                        float nv = (v[nj * 2 + e] - mean) * rstd;
                        float s  = nv * fsig(nv);
                        float mm = s * smw[wn * 64 + ni * 8 + qt * 2 + e];
                        float ov = mm * fsig(mm);
                        if (e == 0) o.x = ov; else o.y = ov;
                    }
                    *reinterpret_cast<float2*>(op + ni * 8 + qt * 2) = o;
                }
            }
        }
    }
}

// ============================ launch ============================
extern "C" void kernel_launch(void* const* d_in, const int* in_sizes, int n_in,
                              void* d_out, int out_size) {
    const float* x  = (const float*)d_in[0];
    const float* W  = (const float*)d_in[1];
    const float* b  = (const float*)d_in[2];
    const float* mw = (const float*)d_in[3];
    float* out = (float*)d_out;

    const size_t M = (size_t)in_sizes[0] / K_DIM;   // 65536

    // 1) x -> fp16
    convert_x_kernel<<<(unsigned)(M * K_DIM / 8 / 256), 256>>>(x);

    // 2) W -> Wt fp16
    dim3 tb(32, 8), tg(N_DIM / 32, K_DIM / 32);
    transpose_W_kernel<<<tg, tb>>>(W);

    // 3) fused GEMM + bias + GroupNorm + Swish chain
    cudaFuncSetAttribute(fused_gemm_gn_swish_kernel,
                         cudaFuncAttributeMaxDynamicSharedMemorySize, SMEM_TOTAL);
    dim3 grid(N_DIM / BN, (unsigned)(M / BM));  // x fastest: N-tiles of one M share A in L2
    fused_gemm_gn_swish_kernel<<<grid, THREADS, SMEM_TOTAL>>>(b, mw, out);
}